// round 4
// baseline (speedup 1.0000x reference)
#include <cuda_runtime.h>
#include <cuda_bf16.h>
#include <cstdint>

// ---------------------------------------------------------------------------
// Problem constants
// ---------------------------------------------------------------------------
#define N_BATCH 8192
#define N_IN    784
#define N_HID   4096
#define N_OUT   10
#define KP8     896      // K padded to 7 * 128 (int8 path)
#define KCH8    7        // number of 128-element K chunks
#define QSCALE  5120.0f
#define INV_QS  (1.0f / 5120.0f)

// ---------------------------------------------------------------------------
// Device scratch (static: no allocation allowed)
// ---------------------------------------------------------------------------
__device__ __align__(16) int8_t g_xlo[(size_t)N_BATCH * KP8];
__device__ __align__(16) int8_t g_xhi[(size_t)N_BATCH * KP8];
__device__ __align__(16) int8_t g_w8 [(size_t)N_HID   * KP8];
// partials: [64 m-blocks][64 n-blocks of 64 cols][128 rows][10 outs]
__device__ float g_part[(size_t)64 * 64 * 128 * N_OUT];

// ---------------------------------------------------------------------------
// Helpers (base sm_103-legal only: cp.async, ldmatrix, mma.sync)
// ---------------------------------------------------------------------------
__device__ __forceinline__ uint32_t smem_to_u32(const void* smem_ptr) {
    uint32_t addr;
    asm("{ .reg .u64 tmp; cvta.to.shared.u64 tmp, %1; cvt.u32.u64 %0, tmp; }"
        : "=r"(addr) : "l"(smem_ptr));
    return addr;
}

__device__ __forceinline__ void cp_async16(uint32_t saddr, const void* gptr) {
    asm volatile("cp.async.cg.shared.global [%0], [%1], 16;"
                 :: "r"(saddr), "l"(gptr));
}
#define CP_COMMIT() asm volatile("cp.async.commit_group;" ::: "memory")
#define CP_WAIT(n)  asm volatile("cp.async.wait_group %0;" :: "n"(n) : "memory")

__device__ __forceinline__ void ldsm_x4(uint32_t& r0, uint32_t& r1,
                                        uint32_t& r2, uint32_t& r3,
                                        uint32_t addr) {
    asm volatile("ldmatrix.sync.aligned.m8n8.x4.shared.b16 {%0,%1,%2,%3}, [%4];"
                 : "=r"(r0), "=r"(r1), "=r"(r2), "=r"(r3) : "r"(addr));
}
__device__ __forceinline__ void ldsm_x2(uint32_t& r0, uint32_t& r1,
                                        uint32_t addr) {
    asm volatile("ldmatrix.sync.aligned.m8n8.x2.shared.b16 {%0,%1}, [%2];"
                 : "=r"(r0), "=r"(r1) : "r"(addr));
}

// int8 MMA: m16n8k32, s8 x s8 -> s32 accumulate (exact)
__device__ __forceinline__ void mma_s8(int* c, const uint32_t* a,
                                       const uint32_t* b) {
    asm volatile(
        "mma.sync.aligned.m16n8k32.row.col.s32.s8.s8.s32 "
        "{%0,%1,%2,%3}, {%4,%5,%6,%7}, {%8,%9}, {%0,%1,%2,%3};"
        : "+r"(c[0]), "+r"(c[1]), "+r"(c[2]), "+r"(c[3])
        : "r"(a[0]), "r"(a[1]), "r"(a[2]), "r"(a[3]), "r"(b[0]), "r"(b[1]));
}

__device__ __forceinline__ uint32_t sw128(uint32_t b) {
    return b ^ ((b >> 3) & 0x70);
}

// ---------------------------------------------------------------------------
// Prep kernels: sign(W1) -> s8 ; x -> exact 2-digit balanced base-256 split
// q = lrint(x*5120), q = 256*q_hi + q_lo, both digits in s8. Pad K to 896.
// ---------------------------------------------------------------------------
__global__ void prep_w_kernel(const float* __restrict__ W1) {
    int idx = blockIdx.x * blockDim.x + threadIdx.x;
    if (idx >= N_HID * KP8) return;
    int r = idx / KP8, k = idx - r * KP8;
    int8_t s = 0;
    if (k < N_IN) {
        float w = W1[(size_t)r * N_IN + k];
        s = (w > 0.0f) ? 1 : ((w < 0.0f) ? -1 : 0);
    }
    g_w8[idx] = s;
}

__global__ void prep_x_kernel(const float* __restrict__ x) {
    int idx = blockIdx.x * blockDim.x + threadIdx.x;
    if (idx >= N_BATCH * KP8) return;
    int r = idx / KP8, k = idx - r * KP8;
    int8_t lo = 0, hi = 0;
    if (k < N_IN) {
        float v = x[(size_t)r * N_IN + k];
        float qs = fminf(fmaxf(v * QSCALE, -32511.0f), 32511.0f);
        int q = __float2int_rn(qs);
        int l = ((q + 128) & 255) - 128;      // balanced low digit [-128,127]
        int h = (q - l) >> 8;                 // high digit [-127,127]
        lo = (int8_t)l;
        hi = (int8_t)h;
    }
    g_xlo[idx] = lo;
    g_xhi[idx] = hi;
}

// ---------------------------------------------------------------------------
// Fused GEMM1 (+bias, clip) + partial GEMM2 kernel
// Grid: (64 n-blocks of 64, 64 m-blocks of 128), 256 threads/CTA
// CTA tile 128x64, warps 4(M) x 2(N), warp tile 32x32, mma m16n8k32 s8
// Two digit accumulators (hi/lo), exact int32, combined in epilogue.
// ---------------------------------------------------------------------------
#define SMEM_B1     0                    // 64 floats
#define SMEM_W2     256                  // 10*64 floats = 2560 B
#define SMEM_T0     4096                 // stage 0: Alo(16K), Ahi(16K), B(8K)
#define SMEM_T1     (SMEM_T0 + 40960)    // stage 1
#define SMEM_H      SMEM_T0              // reuse for h tile: 128*68*4 = 34816 B
#define SMEM_X      SMEM_T1              // reuse for half-exchange (5120 B)
#define SMEM_TOTAL  (SMEM_T1 + 40960)    // 86016 B

__global__ void __launch_bounds__(256, 2)
gemm_fused_kernel(const float* __restrict__ b1, const float* __restrict__ W2)
{
    extern __shared__ char smem[];
    const uint32_t smem_base = smem_to_u32(smem);
    const int tid = threadIdx.x;
    const int wid = tid >> 5;
    const int lid = tid & 31;
    const int nb  = blockIdx.x;       // n-block: 64 hidden cols
    const int mb  = blockIdx.y;       // m-block: 128 batch rows
    const int nbase = nb * 64;

    // stage b1 and W2 slices for this n-range
    {
        float* b1s = reinterpret_cast<float*>(smem + SMEM_B1);
        float* w2s = reinterpret_cast<float*>(smem + SMEM_W2);
        if (tid < 64) b1s[tid] = b1[nbase + tid];
        for (int i = tid; i < N_OUT * 64; i += 256) {
            int o = i >> 6, n = i & 63;
            w2s[i] = W2[(size_t)o * N_HID + nbase + n];
        }
    }

    const int8_t* Alo = g_xlo + (size_t)mb * 128 * KP8;
    const int8_t* Ahi = g_xhi + (size_t)mb * 128 * KP8;
    const int8_t* Bw  = g_w8  + (size_t)nbase * KP8;

    // async-load one 40 KB chunk: A_lo/A_hi 128 rows x 128 B, B 64 rows x 128 B
    auto load_chunk = [&](int kc, uint32_t stage) {
        const int kco = kc * 128;
        #pragma unroll
        for (int t = tid; t < 128 * 8; t += 256) {
            int r = t >> 3, i = t & 7;
            uint32_t so = sw128((r << 7) | (i << 4));
            cp_async16(stage + so,         Alo + (size_t)r * KP8 + kco + i * 16);
            cp_async16(stage + 16384 + so, Ahi + (size_t)r * KP8 + kco + i * 16);
        }
        #pragma unroll
        for (int t = tid; t < 64 * 8; t += 256) {
            int r = t >> 3, i = t & 7;
            cp_async16(stage + 32768 + sw128((r << 7) | (i << 4)),
                       Bw + (size_t)r * KP8 + kco + i * 16);
        }
    };

    const int wm = wid >> 1;    // 0..3  (M: 32 rows each)
    const int wn = wid & 1;     // 0..1  (N: 32 cols each)

    int clo[8][4], chi[8][4];
    #pragma unroll
    for (int t = 0; t < 8; t++)
        #pragma unroll
        for (int a = 0; a < 4; a++) { clo[t][a] = 0; chi[t][a] = 0; }

    load_chunk(0, smem_base + SMEM_T0);
    CP_COMMIT();

    // ldmatrix lane-address components (pre-swizzle)
    const uint32_t a_row = (uint32_t)(wm * 32 + (lid & 15));
    const uint32_t a_byt = (uint32_t)((lid >> 4) << 4);       // 0 or 16
    const uint32_t b_row = (uint32_t)(wn * 32 + (lid & 7));
    const uint32_t b_byt = (uint32_t)(((lid >> 3) & 1) << 4); // 0 or 16

    for (int kc = 0; kc < KCH8; kc++) {
        if (kc + 1 < KCH8) {
            load_chunk(kc + 1, smem_base + ((kc + 1) & 1 ? SMEM_T1 : SMEM_T0));
            CP_COMMIT();
            CP_WAIT(1);
        } else {
            CP_WAIT(0);
        }
        __syncthreads();

        const uint32_t stage = smem_base + ((kc & 1) ? SMEM_T1 : SMEM_T0);
        const uint32_t sa_lo = stage;
        const uint32_t sa_hi = stage + 16384;
        const uint32_t sb    = stage + 32768;

        // last chunk: only k 768..799 are real (784..895 zero-padded): 1 k-step
        const int nsteps = (kc == KCH8 - 1) ? 1 : 4;

        for (int s = 0; s < nsteps; s++) {
            const uint32_t kbyt = s * 32;
            uint32_t bf[2][2];
            #pragma unroll
            for (int j = 0; j < 2; j++)      // two x2 loads cover 4 n-tiles? no:
                ;
            // 4 n-tiles of 8 cols each -> 4 ldsm_x2
            uint32_t bfr[4][2];
            #pragma unroll
            for (int j = 0; j < 4; j++) {
                ldsm_x2(bfr[j][0], bfr[j][1],
                        sb + sw128(((b_row + j * 8) << 7) + kbyt + b_byt));
            }
            #pragma unroll
            for (int i = 0; i < 2; i++) {
                uint32_t af[4];
                ldsm_x4(af[0], af[1], af[2], af[3],
                        sa_lo + sw128(((a_row + i * 16) << 7) + kbyt + a_byt));
                #pragma unroll
                for (int j = 0; j < 4; j++) mma_s8(clo[i * 4 + j], af, bfr[j]);
            }
            #pragma unroll
            for (int i = 0; i < 2; i++) {
                uint32_t af[4];
                ldsm_x4(af[0], af[1], af[2], af[3],
                        sa_hi + sw128(((a_row + i * 16) << 7) + kbyt + a_byt));
                #pragma unroll
                for (int j = 0; j < 4; j++) mma_s8(chi[i * 4 + j], af, bfr[j]);
            }
            (void)bf;
        }
        __syncthreads();
    }

    // ---- epilogue: combine digits, +b1, clip -> h tile (stride 68 floats) ---
    {
        const float* b1s = reinterpret_cast<const float*>(smem + SMEM_B1);
        float* hs = reinterpret_cast<float*>(smem + SMEM_H);
        #pragma unroll
        for (int i = 0; i < 2; i++) {
            #pragma unroll
            for (int j = 0; j < 4; j++) {
                int r0 = wm * 32 + i * 16 + (lid >> 2);
                int cc = wn * 32 + j * 8 + (lid & 3) * 2;
                int q0 = chi[i * 4 + j][0] * 256 + clo[i * 4 + j][0];
                int q1 = chi[i * 4 + j][1] * 256 + clo[i * 4 + j][1];
                int q2 = chi[i * 4 + j][2] * 256 + clo[i * 4 + j][2];
                int q3 = chi[i * 4 + j][3] * 256 + clo[i * 4 + j][3];
                float bb0 = b1s[cc], bb1 = b1s[cc + 1];
                float v0 = fminf(1.0f, fmaxf(-1.0f, (float)q0 * INV_QS + bb0));
                float v1 = fminf(1.0f, fmaxf(-1.0f, (float)q1 * INV_QS + bb1));
                float v2 = fminf(1.0f, fmaxf(-1.0f, (float)q2 * INV_QS + bb0));
                float v3 = fminf(1.0f, fmaxf(-1.0f, (float)q3 * INV_QS + bb1));
                hs[r0 * 68 + cc]           = v0;
                hs[r0 * 68 + cc + 1]       = v1;
                hs[(r0 + 8) * 68 + cc]     = v2;
                hs[(r0 + 8) * 68 + cc + 1] = v3;
            }
        }
    }
    __syncthreads();

    // ---- partial GEMM2: thread = (row, half of 32 cols); halves combined ----
    {
        const int row  = tid >> 1;
        const int half = tid & 1;
        const float* hrow =
            reinterpret_cast<const float*>(smem + SMEM_H) + row * 68 + half * 32;
        const float* w2s =
            reinterpret_cast<const float*>(smem + SMEM_W2) + half * 32;

        float acc[N_OUT];
        #pragma unroll
        for (int o = 0; o < N_OUT; o++) acc[o] = 0.0f;
        #pragma unroll 8
        for (int cidx = 0; cidx < 32; cidx++) {
            float h = hrow[cidx];
            #pragma unroll
            for (int o = 0; o < N_OUT; o++) acc[o] += h * w2s[o * 64 + cidx];
        }

        float* exch = reinterpret_cast<float*>(smem + SMEM_X);
        if (half) {
            #pragma unroll
            for (int o = 0; o < N_OUT; o++) exch[row * N_OUT + o] = acc[o];
        }
        __syncthreads();
        if (!half) {
            const size_t pb = ((size_t)(mb * 64 + nb) * 128 + row) * N_OUT;
            #pragma unroll
            for (int o = 0; o < N_OUT; o++)
                g_part[pb + o] = acc[o] + exch[row * N_OUT + o];
        }
    }
}

// ---------------------------------------------------------------------------
// Final reduce: out[m,o] = b2[o] + sum over 64 n-blocks of partials
// ---------------------------------------------------------------------------
__global__ void reduce_kernel(const float* __restrict__ b2,
                              float* __restrict__ out)
{
    int idx = blockIdx.x * blockDim.x + threadIdx.x;
    if (idx >= N_BATCH * N_OUT) return;
    int m = idx / N_OUT, o = idx - m * N_OUT;
    int mb = m >> 7, r = m & 127;
    float s = b2[o];
    const float* p = g_part + ((size_t)(mb * 64) * 128 + r) * N_OUT + o;
    #pragma unroll
    for (int nc = 0; nc < 64; nc++) s += p[(size_t)nc * 128 * N_OUT];
    out[idx] = s;
}

// ---------------------------------------------------------------------------
// kernel_launch
// ---------------------------------------------------------------------------
extern "C" void kernel_launch(void* const* d_in, const int* in_sizes, int n_in,
                              void* d_out, int out_size)
{
    const float* x  = (const float*)d_in[0];
    const float* W1 = (const float*)d_in[1];
    const float* b1 = (const float*)d_in[2];
    const float* W2 = (const float*)d_in[3];
    const float* b2 = (const float*)d_in[4];
    float* out = (float*)d_out;

    cudaFuncSetAttribute(gemm_fused_kernel,
                         cudaFuncAttributeMaxDynamicSharedMemorySize, SMEM_TOTAL);

    prep_x_kernel<<<(N_BATCH * KP8 + 255) / 256, 256>>>(x);
    prep_w_kernel<<<(N_HID * KP8 + 255) / 256, 256>>>(W1);
    gemm_fused_kernel<<<dim3(64, 64), 256, SMEM_TOTAL>>>(b1, W2);
    reduce_kernel<<<(N_BATCH * N_OUT + 255) / 256, 256>>>(b2, out);
}

// round 12
// speedup vs baseline: 2.0494x; 2.0494x over previous
#include <cuda_runtime.h>
#include <cuda_bf16.h>
#include <cstdint>

// ---------------------------------------------------------------------------
// Problem constants
// ---------------------------------------------------------------------------
#define N_BATCH 8192
#define N_IN    784
#define N_HID   4096
#define N_OUT   10
#define KP      832      // K padded to 13 * 64
#define KCH     13       // number of 64-column K chunks
// real K = 784 = 49 k-steps of 16: chunks 0..11 run 4 steps, chunk 12 runs 1.

// ---------------------------------------------------------------------------
// Device scratch (static: no allocation allowed)
// ---------------------------------------------------------------------------
__device__ __align__(16) __nv_bfloat16 g_xhi[(size_t)N_BATCH * KP];
__device__ __align__(16) __nv_bfloat16 g_xlo[(size_t)N_BATCH * KP];
__device__ __align__(16) __nv_bfloat16 g_wb [(size_t)N_HID   * KP];
// partials: [64 m-blocks][64 n-chunks of 64 cols][128 rows][10 outs]
__device__ float g_part[(size_t)64 * 64 * 128 * N_OUT];

// ---------------------------------------------------------------------------
// Helpers (base sm_103-legal only: cp.async, ldmatrix, mma.sync)
// ---------------------------------------------------------------------------
__device__ __forceinline__ uint32_t smem_to_u32(const void* smem_ptr) {
    uint32_t addr;
    asm("{ .reg .u64 tmp; cvta.to.shared.u64 tmp, %1; cvt.u32.u64 %0, tmp; }"
        : "=r"(addr) : "l"(smem_ptr));
    return addr;
}

__device__ __forceinline__ void cp_async16(uint32_t saddr, const void* gptr) {
    asm volatile("cp.async.cg.shared.global [%0], [%1], 16;"
                 :: "r"(saddr), "l"(gptr));
}
#define CP_COMMIT() asm volatile("cp.async.commit_group;" ::: "memory")
#define CP_WAIT(n)  asm volatile("cp.async.wait_group %0;" :: "n"(n) : "memory")

__device__ __forceinline__ void ldsm_x4(uint32_t& r0, uint32_t& r1,
                                        uint32_t& r2, uint32_t& r3,
                                        uint32_t addr) {
    asm volatile("ldmatrix.sync.aligned.m8n8.x4.shared.b16 {%0,%1,%2,%3}, [%4];"
                 : "=r"(r0), "=r"(r1), "=r"(r2), "=r"(r3) : "r"(addr));
}
__device__ __forceinline__ void ldsm_x2(uint32_t& r0, uint32_t& r1,
                                        uint32_t addr) {
    asm volatile("ldmatrix.sync.aligned.m8n8.x2.shared.b16 {%0,%1}, [%2];"
                 : "=r"(r0), "=r"(r1) : "r"(addr));
}

__device__ __forceinline__ void mma16816(float* c, const uint32_t* a,
                                         const uint32_t* b) {
    asm volatile(
        "mma.sync.aligned.m16n8k16.row.col.f32.bf16.bf16.f32 "
        "{%0,%1,%2,%3}, {%4,%5,%6,%7}, {%8,%9}, {%0,%1,%2,%3};"
        : "+f"(c[0]), "+f"(c[1]), "+f"(c[2]), "+f"(c[3])
        : "r"(a[0]), "r"(a[1]), "r"(a[2]), "r"(a[3]), "r"(b[0]), "r"(b[1]));
}

__device__ __forceinline__ uint32_t sw128(uint32_t b) {
    return b ^ ((b >> 3) & 0x70);
}

// ---------------------------------------------------------------------------
// Prep kernels (4-wide): binarize W1, split x into bf16 hi/lo, pad K to 832
// ---------------------------------------------------------------------------
__global__ void prep_w_kernel(const float* __restrict__ W1) {
    int idx4 = blockIdx.x * blockDim.x + threadIdx.x;   // 4 elems per thread
    if (idx4 >= N_HID * KP / 4) return;
    int idx = idx4 * 4;
    int r = idx / KP, k = idx - r * KP;
    __nv_bfloat16 o[4];
    if (k + 3 < N_IN) {
        float4 w = *reinterpret_cast<const float4*>(W1 + (size_t)r * N_IN + k);
        o[0] = __float2bfloat16((w.x > 0.f) ? 1.f : ((w.x < 0.f) ? -1.f : 0.f));
        o[1] = __float2bfloat16((w.y > 0.f) ? 1.f : ((w.y < 0.f) ? -1.f : 0.f));
        o[2] = __float2bfloat16((w.z > 0.f) ? 1.f : ((w.z < 0.f) ? -1.f : 0.f));
        o[3] = __float2bfloat16((w.w > 0.f) ? 1.f : ((w.w < 0.f) ? -1.f : 0.f));
    } else {
        #pragma unroll
        for (int j = 0; j < 4; j++) {
            float s = 0.0f;
            if (k + j < N_IN) {
                float w = W1[(size_t)r * N_IN + k + j];
                s = (w > 0.f) ? 1.f : ((w < 0.f) ? -1.f : 0.f);
            }
            o[j] = __float2bfloat16(s);
        }
    }
    *reinterpret_cast<uint2*>(g_wb + idx) = *reinterpret_cast<uint2*>(o);
}

__global__ void prep_x_kernel(const float* __restrict__ x) {
    int idx4 = blockIdx.x * blockDim.x + threadIdx.x;
    if (idx4 >= N_BATCH * KP / 4) return;
    int idx = idx4 * 4;
    int r = idx / KP, k = idx - r * KP;
    __nv_bfloat16 hi[4], lo[4];
    if (k + 3 < N_IN) {
        float4 v = *reinterpret_cast<const float4*>(x + (size_t)r * N_IN + k);
        float vv[4] = {v.x, v.y, v.z, v.w};
        #pragma unroll
        for (int j = 0; j < 4; j++) {
            hi[j] = __float2bfloat16(vv[j]);
            lo[j] = __float2bfloat16(vv[j] - __bfloat162float(hi[j]));
        }
    } else {
        #pragma unroll
        for (int j = 0; j < 4; j++) {
            float v = (k + j < N_IN) ? x[(size_t)r * N_IN + k + j] : 0.0f;
            hi[j] = __float2bfloat16(v);
            lo[j] = __float2bfloat16(v - __bfloat162float(hi[j]));
        }
    }
    *reinterpret_cast<uint2*>(g_xhi + idx) = *reinterpret_cast<uint2*>(hi);
    *reinterpret_cast<uint2*>(g_xlo + idx) = *reinterpret_cast<uint2*>(lo);
}

// ---------------------------------------------------------------------------
// Fused GEMM1 (+bias, clip) + partial GEMM2 kernel
// Grid: (32 n-blocks of 128, 64 m-blocks of 128), 256 threads/CTA
// CTA tile 128x128, warps 2(M) x 4(N), warp tile 64x32, mma m16n8k16 bf16
// ---------------------------------------------------------------------------
#define SMEM_B1     0                    // 128 floats
#define SMEM_W2     512                  // 10*128 floats = 5120 B
#define SMEM_T0     6144                 // stage 0: Ah,Al,B (16 KB each)
#define SMEM_T1     (SMEM_T0 + 49152)    // stage 1
#define SMEM_H      SMEM_T0              // reuse for h tile: 128*132*4 B
#define SMEM_TOTAL  (SMEM_T1 + 49152)    // 104448 B

__global__ void __launch_bounds__(256)
gemm_fused_kernel(const float* __restrict__ b1, const float* __restrict__ W2)
{
    extern __shared__ char smem[];
    const uint32_t smem_base = smem_to_u32(smem);
    const int tid = threadIdx.x;
    const int wid = tid >> 5;
    const int lid = tid & 31;
    const int nb  = blockIdx.x;       // n-block: 128 hidden cols
    const int mb  = blockIdx.y;       // m-block: 128 batch rows
    const int nbase = nb * 128;

    // stage b1 and W2 slices for this n-range
    {
        float* b1s = reinterpret_cast<float*>(smem + SMEM_B1);
        float* w2s = reinterpret_cast<float*>(smem + SMEM_W2);
        if (tid < 128) b1s[tid] = b1[nbase + tid];
        for (int i = tid; i < N_OUT * 128; i += 256) {
            int o = i >> 7, n = i & 127;
            w2s[i] = W2[(size_t)o * N_HID + nbase + n];
        }
    }

    const __nv_bfloat16* Ah = g_xhi + (size_t)mb * 128 * KP;
    const __nv_bfloat16* Al = g_xlo + (size_t)mb * 128 * KP;
    const __nv_bfloat16* Bw = g_wb  + (size_t)nbase * KP;

    // async-load one 48 KB chunk (A_hi, A_lo: 128 rows; B: 128 rows; 128 B/row)
    auto load_chunk = [&](int kc, uint32_t stage) {
        const int kco = kc * 64;
        #pragma unroll
        for (int t = tid; t < 128 * 8; t += 256) {
            int r = t >> 3, i = t & 7;
            uint32_t so = sw128((r << 7) | (i << 4));
            cp_async16(stage + so,           Ah + (size_t)r * KP + kco + i * 8);
            cp_async16(stage + 16384 + so,   Al + (size_t)r * KP + kco + i * 8);
            cp_async16(stage + 32768 + so,   Bw + (size_t)r * KP + kco + i * 8);
        }
    };

    const int wm = wid >> 2;    // 0..1
    const int wn = wid & 3;     // 0..3

    float c[16][4];
    #pragma unroll
    for (int t = 0; t < 16; t++)
        #pragma unroll
        for (int a = 0; a < 4; a++) c[t][a] = 0.0f;

    load_chunk(0, smem_base + SMEM_T0);
    CP_COMMIT();

    // precomputed ldmatrix lane offsets (within a tile, before swizzle)
    const uint32_t a_row = (uint32_t)(lid & 15);          // + m-tile base
    const uint32_t a_byt = (uint32_t)((lid >> 4) << 4);   // 0 or 16
    const uint32_t b_row = (uint32_t)(lid & 7);           // + n-tile base
    const uint32_t b_byt = (uint32_t)(((lid >> 3) & 1) << 4);

    // one k-step (16 k-elements) of both hi and lo passes
    auto mma_step = [&](uint32_t sa_hi, uint32_t sa_lo, uint32_t sb, int s) {
        const uint32_t kbyt = s * 32;
        uint32_t bfr[4][2];
        #pragma unroll
        for (int j = 0; j < 4; j++) {
            uint32_t nrow = wn * 32 + j * 8 + b_row;
            ldsm_x2(bfr[j][0], bfr[j][1],
                    sb + sw128((nrow << 7) + kbyt + b_byt));
        }
        #pragma unroll
        for (int i = 0; i < 4; i++) {
            uint32_t af[4];
            uint32_t arow = wm * 64 + i * 16 + a_row;
            ldsm_x4(af[0], af[1], af[2], af[3],
                    sa_hi + sw128((arow << 7) + kbyt + a_byt));
            #pragma unroll
            for (int j = 0; j < 4; j++) mma16816(c[i * 4 + j], af, bfr[j]);
        }
        #pragma unroll
        for (int i = 0; i < 4; i++) {
            uint32_t af[4];
            uint32_t arow = wm * 64 + i * 16 + a_row;
            ldsm_x4(af[0], af[1], af[2], af[3],
                    sa_lo + sw128((arow << 7) + kbyt + a_byt));
            #pragma unroll
            for (int j = 0; j < 4; j++) mma16816(c[i * 4 + j], af, bfr[j]);
        }
    };

    for (int kc = 0; kc < KCH; kc++) {
        if (kc + 1 < KCH) {
            load_chunk(kc + 1, smem_base + ((kc + 1) & 1 ? SMEM_T1 : SMEM_T0));
            CP_COMMIT();
            CP_WAIT(1);
        } else {
            CP_WAIT(0);
        }
        __syncthreads();

        const uint32_t stage = smem_base + ((kc & 1) ? SMEM_T1 : SMEM_T0);
        const uint32_t sa_hi = stage;
        const uint32_t sa_lo = stage + 16384;
        const uint32_t sb    = stage + 32768;

        if (kc == KCH - 1) {
            // last chunk: only k 768..783 are real (784..831 zero) -> 1 k-step
            mma_step(sa_hi, sa_lo, sb, 0);
        } else {
            #pragma unroll
            for (int s = 0; s < 4; s++) mma_step(sa_hi, sa_lo, sb, s);
        }
        __syncthreads();
    }

    // ---- epilogue: +b1, clip -> h tile in smem (stride 132 floats) ----
    {
        const float* b1s = reinterpret_cast<const float*>(smem + SMEM_B1);
        float* hs = reinterpret_cast<float*>(smem + SMEM_H);
        #pragma unroll
        for (int i = 0; i < 4; i++) {
            #pragma unroll
            for (int j = 0; j < 4; j++) {
                int r0 = wm * 64 + i * 16 + (lid >> 2);
                int cc = wn * 32 + j * 8 + (lid & 3) * 2;
                float bb0 = b1s[cc], bb1 = b1s[cc + 1];
                float v0 = fminf(1.0f, fmaxf(-1.0f, c[i * 4 + j][0] + bb0));
                float v1 = fminf(1.0f, fmaxf(-1.0f, c[i * 4 + j][1] + bb1));
                float v2 = fminf(1.0f, fmaxf(-1.0f, c[i * 4 + j][2] + bb0));
                float v3 = fminf(1.0f, fmaxf(-1.0f, c[i * 4 + j][3] + bb1));
                hs[r0 * 132 + cc]           = v0;
                hs[r0 * 132 + cc + 1]       = v1;
                hs[(r0 + 8) * 132 + cc]     = v2;
                hs[(r0 + 8) * 132 + cc + 1] = v3;
            }
        }
    }
    __syncthreads();

    // ---- partial GEMM2: thread = (row, half of 64 cols) -> g_part ----
    {
        const int row  = tid >> 1;
        const int half = tid & 1;
        const float* hrow =
            reinterpret_cast<const float*>(smem + SMEM_H) + row * 132 + half * 64;
        const float* w2s =
            reinterpret_cast<const float*>(smem + SMEM_W2) + half * 64;

        float acc[N_OUT];
        #pragma unroll
        for (int o = 0; o < N_OUT; o++) acc[o] = 0.0f;
        #pragma unroll 8
        for (int cidx = 0; cidx < 64; cidx++) {
            float h = hrow[cidx];
            #pragma unroll
            for (int o = 0; o < N_OUT; o++) acc[o] += h * w2s[o * 128 + cidx];
        }
        const size_t pb =
            ((size_t)(mb * 64 + nb * 2 + half) * 128 + row) * N_OUT;
        #pragma unroll
        for (int o = 0; o < N_OUT; o++) g_part[pb + o] = acc[o];
    }
}

// ---------------------------------------------------------------------------
// Final reduce: out[m,o] = b2[o] + sum over 64 n-chunks of partials
// ---------------------------------------------------------------------------
__global__ void reduce_kernel(const float* __restrict__ b2,
                              float* __restrict__ out)
{
    int idx = blockIdx.x * blockDim.x + threadIdx.x;
    if (idx >= N_BATCH * N_OUT) return;
    int m = idx / N_OUT, o = idx - m * N_OUT;
    int mb = m >> 7, r = m & 127;
    float s = b2[o];
    const float* p = g_part + ((size_t)(mb * 64) * 128 + r) * N_OUT + o;
    #pragma unroll
    for (int nc = 0; nc < 64; nc++) s += p[(size_t)nc * 128 * N_OUT];
    out[idx] = s;
}

// ---------------------------------------------------------------------------
// kernel_launch
// ---------------------------------------------------------------------------
extern "C" void kernel_launch(void* const* d_in, const int* in_sizes, int n_in,
                              void* d_out, int out_size)
{
    const float* x  = (const float*)d_in[0];
    const float* W1 = (const float*)d_in[1];
    const float* b1 = (const float*)d_in[2];
    const float* W2 = (const float*)d_in[3];
    const float* b2 = (const float*)d_in[4];
    float* out = (float*)d_out;

    cudaFuncSetAttribute(gemm_fused_kernel,
                         cudaFuncAttributeMaxDynamicSharedMemorySize, SMEM_TOTAL);

    prep_x_kernel<<<(N_BATCH * KP / 4 + 255) / 256, 256>>>(x);
    prep_w_kernel<<<(N_HID * KP / 4 + 255) / 256, 256>>>(W1);
    gemm_fused_kernel<<<dim3(32, 64), 256, SMEM_TOTAL>>>(b1, W2);
    reduce_kernel<<<(N_BATCH * N_OUT + 255) / 256, 256>>>(b2, out);
}

// round 15
// speedup vs baseline: 2.1136x; 1.0313x over previous
#include <cuda_runtime.h>
#include <cuda_bf16.h>
#include <cstdint>

// ---------------------------------------------------------------------------
// Problem constants
// ---------------------------------------------------------------------------
#define N_BATCH 8192
#define N_IN    784
#define N_HID   4096
#define N_OUT   10
#define KP      832      // K padded to 13 * 64
#define KCH     13       // number of 64-column K chunks
// real K = 784 = 49 k-steps of 16: chunks 0..11 run 4 steps, chunk 12 runs 1.

// ---------------------------------------------------------------------------
// Device scratch (static: no allocation allowed)
// ---------------------------------------------------------------------------
__device__ __align__(16) __nv_bfloat16 g_xhi[(size_t)N_BATCH * KP];
__device__ __align__(16) __nv_bfloat16 g_xlo[(size_t)N_BATCH * KP];
__device__ __align__(16) __nv_bfloat16 g_wb [(size_t)N_HID   * KP];
// partials: [64 m-blocks][16 n-blocks of 256 cols][128 rows][10 outs]
__device__ float g_part[(size_t)64 * 16 * 128 * N_OUT];

// ---------------------------------------------------------------------------
// Helpers (base sm_103-legal only: cp.async, ldmatrix, mma.sync)
// ---------------------------------------------------------------------------
__device__ __forceinline__ uint32_t smem_to_u32(const void* smem_ptr) {
    uint32_t addr;
    asm("{ .reg .u64 tmp; cvta.to.shared.u64 tmp, %1; cvt.u32.u64 %0, tmp; }"
        : "=r"(addr) : "l"(smem_ptr));
    return addr;
}

__device__ __forceinline__ void cp_async16(uint32_t saddr, const void* gptr) {
    asm volatile("cp.async.cg.shared.global [%0], [%1], 16;"
                 :: "r"(saddr), "l"(gptr));
}
#define CP_COMMIT() asm volatile("cp.async.commit_group;" ::: "memory")
#define CP_WAIT(n)  asm volatile("cp.async.wait_group %0;" :: "n"(n) : "memory")

__device__ __forceinline__ void ldsm_x4(uint32_t& r0, uint32_t& r1,
                                        uint32_t& r2, uint32_t& r3,
                                        uint32_t addr) {
    asm volatile("ldmatrix.sync.aligned.m8n8.x4.shared.b16 {%0,%1,%2,%3}, [%4];"
                 : "=r"(r0), "=r"(r1), "=r"(r2), "=r"(r3) : "r"(addr));
}

__device__ __forceinline__ void mma16816(float* c, const uint32_t* a,
                                         const uint32_t* b) {
    asm volatile(
        "mma.sync.aligned.m16n8k16.row.col.f32.bf16.bf16.f32 "
        "{%0,%1,%2,%3}, {%4,%5,%6,%7}, {%8,%9}, {%0,%1,%2,%3};"
        : "+f"(c[0]), "+f"(c[1]), "+f"(c[2]), "+f"(c[3])
        : "r"(a[0]), "r"(a[1]), "r"(a[2]), "r"(a[3]), "r"(b[0]), "r"(b[1]));
}

__device__ __forceinline__ uint32_t sw128(uint32_t b) {
    return b ^ ((b >> 3) & 0x70);
}

// ---------------------------------------------------------------------------
// Prep kernels (4-wide): binarize W1, split x into bf16 hi/lo, pad K to 832
// ---------------------------------------------------------------------------
__global__ void prep_w_kernel(const float* __restrict__ W1) {
    int idx4 = blockIdx.x * blockDim.x + threadIdx.x;   // 4 elems per thread
    if (idx4 >= N_HID * KP / 4) return;
    int idx = idx4 * 4;
    int r = idx / KP, k = idx - r * KP;
    __nv_bfloat16 o[4];
    if (k + 3 < N_IN) {
        float4 w = *reinterpret_cast<const float4*>(W1 + (size_t)r * N_IN + k);
        o[0] = __float2bfloat16((w.x > 0.f) ? 1.f : ((w.x < 0.f) ? -1.f : 0.f));
        o[1] = __float2bfloat16((w.y > 0.f) ? 1.f : ((w.y < 0.f) ? -1.f : 0.f));
        o[2] = __float2bfloat16((w.z > 0.f) ? 1.f : ((w.z < 0.f) ? -1.f : 0.f));
        o[3] = __float2bfloat16((w.w > 0.f) ? 1.f : ((w.w < 0.f) ? -1.f : 0.f));
    } else {
        #pragma unroll
        for (int j = 0; j < 4; j++) {
            float s = 0.0f;
            if (k + j < N_IN) {
                float w = W1[(size_t)r * N_IN + k + j];
                s = (w > 0.f) ? 1.f : ((w < 0.f) ? -1.f : 0.f);
            }
            o[j] = __float2bfloat16(s);
        }
    }
    *reinterpret_cast<uint2*>(g_wb + idx) = *reinterpret_cast<uint2*>(o);
}

__global__ void prep_x_kernel(const float* __restrict__ x) {
    int idx4 = blockIdx.x * blockDim.x + threadIdx.x;
    if (idx4 >= N_BATCH * KP / 4) return;
    int idx = idx4 * 4;
    int r = idx / KP, k = idx - r * KP;
    __nv_bfloat16 hi[4], lo[4];
    if (k + 3 < N_IN) {
        float4 v = *reinterpret_cast<const float4*>(x + (size_t)r * N_IN + k);
        float vv[4] = {v.x, v.y, v.z, v.w};
        #pragma unroll
        for (int j = 0; j < 4; j++) {
            hi[j] = __float2bfloat16(vv[j]);
            lo[j] = __float2bfloat16(vv[j] - __bfloat162float(hi[j]));
        }
    } else {
        #pragma unroll
        for (int j = 0; j < 4; j++) {
            float v = (k + j < N_IN) ? x[(size_t)r * N_IN + k + j] : 0.0f;
            hi[j] = __float2bfloat16(v);
            lo[j] = __float2bfloat16(v - __bfloat162float(hi[j]));
        }
    }
    *reinterpret_cast<uint2*>(g_xhi + idx) = *reinterpret_cast<uint2*>(hi);
    *reinterpret_cast<uint2*>(g_xlo + idx) = *reinterpret_cast<uint2*>(lo);
}

// ---------------------------------------------------------------------------
// Fused GEMM1 (+bias, clip) + partial GEMM2 kernel
// Grid: (16 n-blocks of 256, 64 m-blocks of 128), 512 threads/CTA
// CTA tile 128x256, warps 4(M) x 4(N), warp tile 32x64, mma m16n8k16 bf16
// 1 CTA/SM (160 KB smem), 16 warps = 4/SMSP. Bytes/FLOP cut 33% vs 128x128.
// ---------------------------------------------------------------------------
#define SMEM_B1     0                    // 256 floats  [0, 1024)
#define SMEM_W2     1024                 // 2560 floats [1024, 11264)
#define SMEM_X      11264                // exch 128*3*10 f [11264, 26624)
#define SMEM_T0     32768                // stage: Ah 16K, Al 16K, B 32K
#define SMEM_T1     (SMEM_T0 + 65536)    // stage 1
#define SMEM_H      SMEM_T0              // h half-tile 128*132*4 = 67584 B
#define SMEM_TOTAL  (SMEM_T1 + 65536)    // 163840 B

__global__ void __launch_bounds__(512, 1)
gemm_fused_kernel(const float* __restrict__ b1, const float* __restrict__ W2)
{
    extern __shared__ char smem[];
    const uint32_t smem_base = smem_to_u32(smem);
    const int tid = threadIdx.x;
    const int wid = tid >> 5;
    const int lid = tid & 31;
    const int nb  = blockIdx.x;       // n-block: 256 hidden cols
    const int mb  = blockIdx.y;       // m-block: 128 batch rows
    const int nbase = nb * 256;

    // stage b1 and W2 slices for this n-range
    {
        float* b1s = reinterpret_cast<float*>(smem + SMEM_B1);
        float* w2s = reinterpret_cast<float*>(smem + SMEM_W2);
        if (tid < 256) b1s[tid] = b1[nbase + tid];
        for (int i = tid; i < N_OUT * 256; i += 512) {
            int o = i >> 8, n = i & 255;
            w2s[i] = W2[(size_t)o * N_HID + nbase + n];
        }
    }

    const __nv_bfloat16* Ah = g_xhi + (size_t)mb * 128 * KP;
    const __nv_bfloat16* Al = g_xlo + (size_t)mb * 128 * KP;
    const __nv_bfloat16* Bw = g_wb  + (size_t)nbase * KP;

    // async-load one 64 KB chunk (A_hi, A_lo: 128 rows; B: 256 rows; 128 B/row)
    auto load_chunk = [&](int kc, uint32_t stage) {
        const int kco = kc * 64;
        #pragma unroll
        for (int t = tid; t < 128 * 8; t += 512) {
            int r = t >> 3, i = t & 7;
            uint32_t so = sw128((r << 7) | (i << 4));
            cp_async16(stage + so,           Ah + (size_t)r * KP + kco + i * 8);
            cp_async16(stage + 16384 + so,   Al + (size_t)r * KP + kco + i * 8);
        }
        #pragma unroll
        for (int t = tid; t < 256 * 8; t += 512) {
            int r = t >> 3, i = t & 7;
            cp_async16(stage + 32768 + sw128((r << 7) | (i << 4)),
                       Bw + (size_t)r * KP + kco + i * 8);
        }
    };

    const int wm = wid >> 2;    // 0..3  (M: 32 rows each)
    const int wn = wid & 3;     // 0..3  (N: 64 cols each)

    float c[16][4];             // [i*8+j]: i = m-tile (2), j = n-tile (8)
    #pragma unroll
    for (int t = 0; t < 16; t++)
        #pragma unroll
        for (int a = 0; a < 4; a++) c[t][a] = 0.0f;

    load_chunk(0, smem_base + SMEM_T0);
    CP_COMMIT();

    // ldmatrix lane-address components (pre-swizzle), same for A and B x4 loads
    const uint32_t lrow = (uint32_t)(lid & 15);
    const uint32_t lbyt = (uint32_t)((lid >> 4) << 4);   // 0 or 16

    // one k-step (16 k-elements) of both hi and lo passes
    auto mma_step = [&](uint32_t sa_hi, uint32_t sa_lo, uint32_t sb, int s) {
        const uint32_t kbyt = s * 32;
        uint32_t bfr[8][2];
        #pragma unroll
        for (int jj = 0; jj < 4; jj++) {     // each x4 covers 2 n-tiles
            uint32_t t0, t1, t2, t3;
            uint32_t nrow = wn * 64 + jj * 16 + lrow;
            ldsm_x4(t0, t1, t2, t3, sb + sw128((nrow << 7) + kbyt + lbyt));
            bfr[jj * 2 + 0][0] = t0; bfr[jj * 2 + 0][1] = t2;
            bfr[jj * 2 + 1][0] = t1; bfr[jj * 2 + 1][1] = t3;
        }
        #pragma unroll
        for (int i = 0; i < 2; i++) {
            uint32_t af[4];
            uint32_t arow = wm * 32 + i * 16 + lrow;
            ldsm_x4(af[0], af[1], af[2], af[3],
                    sa_hi + sw128((arow << 7) + kbyt + lbyt));
            #pragma unroll
            for (int j = 0; j < 8; j++) mma16816(c[i * 8 + j], af, bfr[j]);
        }
        #pragma unroll
        for (int i = 0; i < 2; i++) {
            uint32_t af[4];
            uint32_t arow = wm * 32 + i * 16 + lrow;
            ldsm_x4(af[0], af[1], af[2], af[3],
                    sa_lo + sw128((arow << 7) + kbyt + lbyt));
            #pragma unroll
            for (int j = 0; j < 8; j++) mma16816(c[i * 8 + j], af, bfr[j]);
        }
    };

    for (int kc = 0; kc < KCH; kc++) {
        if (kc + 1 < KCH) {
            load_chunk(kc + 1, smem_base + ((kc + 1) & 1 ? SMEM_T1 : SMEM_T0));
            CP_COMMIT();
            CP_WAIT(1);
        } else {
            CP_WAIT(0);
        }
        __syncthreads();

        const uint32_t stage = smem_base + ((kc & 1) ? SMEM_T1 : SMEM_T0);
        const uint32_t sa_hi = stage;
        const uint32_t sa_lo = stage + 16384;
        const uint32_t sb    = stage + 32768;

        if (kc == KCH - 1) {
            // last chunk: only k 768..783 are real (784..831 zero) -> 1 k-step
            mma_step(sa_hi, sa_lo, sb, 0);
        } else {
            #pragma unroll
            for (int s = 0; s < 4; s++) mma_step(sa_hi, sa_lo, sb, s);
        }
        __syncthreads();
    }

    // ---- epilogue in two 128-col halves: +b1, clip -> h half-tile,
    //      then strided conflict-free partial GEMM2 ----
    const int row = tid >> 2;         // 0..127
    const int q   = tid & 3;          // column group within a 128-col half
    float acc[N_OUT];
    #pragma unroll
    for (int o = 0; o < N_OUT; o++) acc[o] = 0.0f;

    const float* b1s = reinterpret_cast<const float*>(smem + SMEM_B1);
    const float* w2s = reinterpret_cast<const float*>(smem + SMEM_W2);
    float* hs = reinterpret_cast<float*>(smem + SMEM_H);

    #pragma unroll
    for (int hf = 0; hf < 2; hf++) {
        // warps wn in {2hf, 2hf+1} own this half's columns
        if ((wn >> 1) == hf) {
            const int ncl = (wn & 1) * 64;     // local col base in half-tile
            #pragma unroll
            for (int i = 0; i < 2; i++) {
                #pragma unroll
                for (int j = 0; j < 8; j++) {
                    int r0 = wm * 32 + i * 16 + (lid >> 2);
                    int cc = ncl + j * 8 + (lid & 3) * 2;
                    int cg = hf * 128 + cc;
                    float bb0 = b1s[cg], bb1 = b1s[cg + 1];
                    float v0 = fminf(1.f, fmaxf(-1.f, c[i * 8 + j][0] + bb0));
                    float v1 = fminf(1.f, fmaxf(-1.f, c[i * 8 + j][1] + bb1));
                    float v2 = fminf(1.f, fmaxf(-1.f, c[i * 8 + j][2] + bb0));
                    float v3 = fminf(1.f, fmaxf(-1.f, c[i * 8 + j][3] + bb1));
                    hs[r0 * 132 + cc]           = v0;
                    hs[r0 * 132 + cc + 1]       = v1;
                    hs[(r0 + 8) * 132 + cc]     = v2;
                    hs[(r0 + 8) * 132 + cc + 1] = v3;
                }
            }
        }
        __syncthreads();
        // GEMM2 partial over this half: thread (row, q) reads cols q, q+4, ...
        // bank = (4*row + q + 4k) % 32 -> all 32 lanes distinct: conflict-free
        #pragma unroll 8
        for (int k = 0; k < 32; k++) {
            int cl = q + 4 * k;                 // 0..127 within half
            float h = hs[row * 132 + cl];
            #pragma unroll
            for (int o = 0; o < N_OUT; o++)
                acc[o] += h * w2s[o * 256 + hf * 128 + cl];
        }
        __syncthreads();   // before next half overwrites the h tile
    }

    // combine the 4 q-groups per row, write partials
    float* exch = reinterpret_cast<float*>(smem + SMEM_X);
    if (q) {
        #pragma unroll
        for (int o = 0; o < N_OUT; o++)
            exch[(row * 3 + (q - 1)) * N_OUT + o] = acc[o];
    }
    __syncthreads();
    if (q == 0) {
        const size_t pb = ((size_t)(mb * 16 + nb) * 128 + row) * N_OUT;
        #pragma unroll
        for (int o = 0; o < N_OUT; o++) {
            float s = acc[o];
            #pragma unroll
            for (int g = 0; g < 3; g++)
                s += exch[(row * 3 + g) * N_OUT + o];
            g_part[pb + o] = s;
        }
    }
}

// ---------------------------------------------------------------------------
// Final reduce: out[m,o] = b2[o] + sum over 16 n-blocks of partials
// ---------------------------------------------------------------------------
__global__ void reduce_kernel(const float* __restrict__ b2,
                              float* __restrict__ out)
{
    int idx = blockIdx.x * blockDim.x + threadIdx.x;
    if (idx >= N_BATCH * N_OUT) return;
    int m = idx / N_OUT, o = idx - m * N_OUT;
    int mb = m >> 7, r = m & 127;
    float s = b2[o];
    const float* p = g_part + ((size_t)(mb * 16) * 128 + r) * N_OUT + o;
    #pragma unroll
    for (int nc = 0; nc < 16; nc++) s += p[(size_t)nc * 128 * N_OUT];
    out[idx] = s;
}

// ---------------------------------------------------------------------------
// kernel_launch
// ---------------------------------------------------------------------------
extern "C" void kernel_launch(void* const* d_in, const int* in_sizes, int n_in,
                              void* d_out, int out_size)
{
    const float* x  = (const float*)d_in[0];
    const float* W1 = (const float*)d_in[1];
    const float* b1 = (const float*)d_in[2];
    const float* W2 = (const float*)d_in[3];
    const float* b2 = (const float*)d_in[4];
    float* out = (float*)d_out;

    cudaFuncSetAttribute(gemm_fused_kernel,
                         cudaFuncAttributeMaxDynamicSharedMemorySize, SMEM_TOTAL);

    prep_x_kernel<<<(N_BATCH * KP / 4 + 255) / 256, 256>>>(x);
    prep_w_kernel<<<(N_HID * KP / 4 + 255) / 256, 256>>>(W1);
    gemm_fused_kernel<<<dim3(16, 64), 512, SMEM_TOTAL>>>(b1, W2);
    reduce_kernel<<<(N_BATCH * N_OUT + 255) / 256, 256>>>(b2, out);
}